// round 17
// baseline (speedup 1.0000x reference)
#include <cuda_runtime.h>
#include <cuda_fp16.h>
#include <math.h>
#include <stdint.h>

#define B_DIM   8
#define HW_DIM  3136
#define C_DIM   256
#define NROWS   (B_DIM * HW_DIM)        // 25088
#define JT      64                      // j tile
#define NJT     (HW_DIM / JT)           // 49

// fused smem (bytes). Xi fragment-major (32KB). Xj pitch 36 u4, T pitch 12 u4
// (proven conflict-free). S ping-pong fragment-major 2x8KB.
#define XP      36
#define TP      12
#define SM_XI   0                       // 32768
#define SM_XJ0  32768                   // 36864
#define SM_XJ1  69632                   // 36864
#define SM_TT0  106496                  // 49152
#define SM_TT1  155648                  // 49152
#define SM_SS0  204800                  // 8192
#define SM_SS1  212992                  // 8192
#define SM_TOT  221184

// transform_mma smem
#define TM_WT   0
#define TM_XT   147456
#define TM_TOT  184320

// device-global scratch (fp16)
__device__ __align__(16) unsigned short g_xn[(size_t)NROWS * C_DIM];          // xn rows [row][c]
__device__ __align__(16) unsigned short g_xa[(size_t)NROWS * C_DIM];          // xn A-frag order
__device__ __align__(16) unsigned short g_xh[(size_t)NROWS * C_DIM];          // raw x fp16
__device__ __align__(16) unsigned short g_wt[(size_t)C_DIM * C_DIM];          // W^T [c][k]
__device__ __align__(16) unsigned short g_tt[(size_t)B_DIM * C_DIM * HW_DIM]; // t [b][c][hw]

__device__ __forceinline__ uint32_t h2pack(float a, float b) {
    __half2 h = __floats2half2_rn(a, b);
    return *reinterpret_cast<uint32_t*>(&h);
}
__device__ __forceinline__ uint32_t smem_u32(const void* p) {
    uint32_t a;
    asm("{ .reg .u64 t; cvta.to.shared.u64 t, %1; cvt.u32.u64 %0, t; }" : "=r"(a) : "l"(p));
    return a;
}
__device__ __forceinline__ void cp16(uint32_t dst, const void* src) {
    asm volatile("{ .reg .u64 g; cvta.to.global.u64 g, %1;"
                 " cp.async.cg.shared.global [%0], [g], 16; }" :: "r"(dst), "l"(src));
}
#define CP_COMMIT() asm volatile("cp.async.commit_group;" ::: "memory")
#define CP_WAIT0()  asm volatile("cp.async.wait_group 0;" ::: "memory")
#define CP_WAIT1()  asm volatile("cp.async.wait_group 1;" ::: "memory")

__device__ __forceinline__ void mma16(float* d, uint32_t a0, uint32_t a1,
                                      uint32_t a2, uint32_t a3,
                                      uint32_t b0, uint32_t b1) {
    asm volatile(
        "mma.sync.aligned.m16n8k16.row.col.f32.f16.f16.f32 "
        "{%0,%1,%2,%3}, {%4,%5,%6,%7}, {%8,%9}, {%0,%1,%2,%3};"
        : "+f"(d[0]), "+f"(d[1]), "+f"(d[2]), "+f"(d[3])
        : "r"(a0), "r"(a1), "r"(a2), "r"(a3), "r"(b0), "r"(b1));
}

// ---------------------------------------------------------------------------
// Kernel A: L2 normalize -> g_xn (fp16 rows) and raw x -> g_xh (fp16)
// ---------------------------------------------------------------------------
__global__ void norm_kernel(const float* __restrict__ x) {
    int row  = blockIdx.x * 8 + threadIdx.y;
    int lane = threadIdx.x;
    const float4* xr = reinterpret_cast<const float4*>(x) + (size_t)row * (C_DIM / 4);
    float4 v0 = xr[lane];
    float4 v1 = xr[lane + 32];
    float s = v0.x*v0.x + v0.y*v0.y + v0.z*v0.z + v0.w*v0.w
            + v1.x*v1.x + v1.y*v1.y + v1.z*v1.z + v1.w*v1.w;
#pragma unroll
    for (int off = 16; off > 0; off >>= 1) s += __shfl_xor_sync(0xffffffffu, s, off);
    float inv = rsqrtf(fmaxf(s, 1e-12f));
    uint2* oh = reinterpret_cast<uint2*>(g_xh) + (size_t)row * (C_DIM / 4);
    oh[lane]      = make_uint2(h2pack(v0.x, v0.y), h2pack(v0.z, v0.w));
    oh[lane + 32] = make_uint2(h2pack(v1.x, v1.y), h2pack(v1.z, v1.w));
    uint2* o = reinterpret_cast<uint2*>(g_xn) + (size_t)row * (C_DIM / 4);
    o[lane]      = make_uint2(h2pack(v0.x*inv, v0.y*inv), h2pack(v0.z*inv, v0.w*inv));
    o[lane + 32] = make_uint2(h2pack(v1.x*inv, v1.y*inv), h2pack(v1.z*inv, v1.w*inv));
}

// ---------------------------------------------------------------------------
// Kernel A2: W^T -> g_wt[c][k] fp16
// ---------------------------------------------------------------------------
__global__ void wt_kernel(const float* __restrict__ W) {
    int c = blockIdx.x, k = threadIdx.x;
    g_wt[(size_t)c * C_DIM + k] = __half_as_ushort(__float2half_rn(W[(size_t)k * C_DIM + c]));
}

// ---------------------------------------------------------------------------
// Kernel A3: relayout g_xn -> g_xa in A-fragment order (proven R14/R15).
// ---------------------------------------------------------------------------
__global__ __launch_bounds__(256)
void xa_kernel() {
    __shared__ unsigned short sx[64 * 272];
    size_t row0 = (size_t)blockIdx.x * 64;
    int tid = threadIdx.x;
#pragma unroll
    for (int q = 0; q < 8; q++) {
        int idx = tid + q * 256, r = idx >> 5, c4 = idx & 31;
        *reinterpret_cast<uint4*>(&sx[r * 272 + c4 * 8]) =
            *reinterpret_cast<const uint4*>(&g_xn[(row0 + r) * C_DIM + c4 * 8]);
    }
    __syncthreads();
#pragma unroll
    for (int q = 0; q < 8; q++) {
        int o = tid + q * 256;
        int g = o >> 9, chunk = (o >> 5) & 15, lane = o & 31;
        int gid = lane >> 2, tig = lane & 3;
        int kc = chunk >> 1, ss = chunk & 1;
        int k0 = 8 * (4 * kc + tig) + 4 * ss;
        int rb = g * 16 + gid;
        uint32_t w0 = *reinterpret_cast<const uint32_t*>(&sx[rb * 272 + k0]);
        uint32_t w1 = *reinterpret_cast<const uint32_t*>(&sx[(rb + 8) * 272 + k0]);
        uint32_t w2 = *reinterpret_cast<const uint32_t*>(&sx[rb * 272 + k0 + 2]);
        uint32_t w3 = *reinterpret_cast<const uint32_t*>(&sx[(rb + 8) * 272 + k0 + 2]);
        *reinterpret_cast<uint4*>(&g_xa[row0 * C_DIM + (size_t)o * 8]) =
            make_uint4(w0, w1, w2, w3);
    }
}

// ---------------------------------------------------------------------------
// Kernel B: t = x @ W on fp16 tensor cores; stored transposed: g_tt[b][c][hw]
// ---------------------------------------------------------------------------
__global__ __launch_bounds__(256)
void transform_mma() {
    extern __shared__ char smem[];
    uint32_t sbase = smem_u32(smem);
    const uint4* Wt4 = reinterpret_cast<const uint4*>(smem + TM_WT);
    const uint4* X4  = reinterpret_cast<const uint4*>(smem + TM_XT);
    __half*      stg = reinterpret_cast<__half*>(smem + TM_XT);

    int row0 = blockIdx.x * 64;
    int tid = threadIdx.x, w = tid >> 5, lane = tid & 31;
    int gid = lane >> 2, tig = lane & 3;
    int wr = w & 1, wn = w >> 1;

#pragma unroll
    for (int q = 0; q < 32; q++) {
        int idx = tid + q * 256, r = idx >> 5, c4 = idx & 31;
        cp16(sbase + TM_WT + (uint32_t)(r * XP + c4) * 16,
             g_wt + (size_t)r * C_DIM + c4 * 8);
    }
#pragma unroll
    for (int q = 0; q < 8; q++) {
        int idx = tid + q * 256, r = idx >> 5, c4 = idx & 31;
        cp16(sbase + TM_XT + (uint32_t)(r * XP + c4) * 16,
             g_xh + (size_t)(row0 + r) * C_DIM + c4 * 8);
    }
    CP_COMMIT(); CP_WAIT0();
    __syncthreads();

    float yacc[2][8][4];
#pragma unroll
    for (int mb = 0; mb < 2; mb++)
#pragma unroll
        for (int nt = 0; nt < 8; nt++)
#pragma unroll
            for (int q = 0; q < 4; q++) yacc[mb][nt][q] = 0.f;

#pragma unroll
    for (int kc = 0; kc < 8; kc++) {
        uint4 Ag[2], Ag8[2];
#pragma unroll
        for (int mb = 0; mb < 2; mb++) {
            int r1 = 32 * wr + 16 * mb + gid;
            Ag[mb]  = X4[r1 * XP + 4 * kc + tig];
            Ag8[mb] = X4[(r1 + 8) * XP + 4 * kc + tig];
        }
#pragma unroll
        for (int nt = 0; nt < 8; nt++) {
            int c = 64 * wn + 8 * nt + gid;
            uint4 Bv = Wt4[c * XP + 4 * kc + tig];
            const uint32_t* bn = reinterpret_cast<const uint32_t*>(&Bv);
#pragma unroll
            for (int ss = 0; ss < 2; ss++)
#pragma unroll
                for (int mb = 0; mb < 2; mb++) {
                    const uint32_t* ag  = reinterpret_cast<const uint32_t*>(&Ag[mb]);
                    const uint32_t* ag8 = reinterpret_cast<const uint32_t*>(&Ag8[mb]);
                    mma16(yacc[mb][nt], ag[2*ss], ag8[2*ss], ag[2*ss+1], ag8[2*ss+1],
                          bn[2*ss], bn[2*ss+1]);
                }
        }
    }
    __syncthreads();

#pragma unroll
    for (int mb = 0; mb < 2; mb++)
#pragma unroll
        for (int nt = 0; nt < 8; nt++) {
            int r1 = 32 * wr + 16 * mb + gid;
            int c  = 64 * wn + 8 * nt + 2 * tig;
            stg[c * 72 + r1]           = __float2half_rn(yacc[mb][nt][0]);
            stg[(c + 1) * 72 + r1]     = __float2half_rn(yacc[mb][nt][1]);
            stg[c * 72 + r1 + 8]       = __float2half_rn(yacc[mb][nt][2]);
            stg[(c + 1) * 72 + r1 + 8] = __float2half_rn(yacc[mb][nt][3]);
        }
    __syncthreads();

    int bb = row0 / HW_DIM, hw0 = row0 - bb * HW_DIM;
#pragma unroll
    for (int p = 0; p < 4; p++) {
        int c = p * 64 + (tid >> 2), ch = tid & 3;
        uint4 v  = *reinterpret_cast<const uint4*>(&stg[c * 72 + ch * 16]);
        uint4 v2 = *reinterpret_cast<const uint4*>(&stg[c * 72 + ch * 16 + 8]);
        *reinterpret_cast<uint4*>(
            &g_tt[((size_t)bb * C_DIM + c) * HW_DIM + hw0 + ch * 16]) = v;
        *reinterpret_cast<uint4*>(
            &g_tt[((size_t)bb * C_DIM + c) * HW_DIM + hw0 + ch * 16 + 8]) = v2;
    }
}

// ---------------------------------------------------------------------------
// Kernel C: fused pass; software-pipelined (ph1(m) || ph2(m-1), two
// independent mma chains per warp) + hoisted constant-offset addressing.
// Schedule/commit groups from R13 (proven); addressing from R15 (proven).
// ---------------------------------------------------------------------------
__global__ __launch_bounds__(256)
void ppm_fused(float* __restrict__ y) {
    extern __shared__ char smem[];
    uint32_t sbase = smem_u32(smem);
    const uint4* XiF = reinterpret_cast<const uint4*>(smem + SM_XI);

    int b  = blockIdx.y;
    int i0 = blockIdx.x * JT;
    const unsigned short* Xg  = g_xn + (size_t)b * HW_DIM * C_DIM;
    const unsigned short* Agm = g_xa + ((size_t)b * HW_DIM + i0) * C_DIM;
    const unsigned short* Tg  = g_tt + (size_t)b * C_DIM * HW_DIM;

    int tid = threadIdx.x, w = tid >> 5, lane = tid & 31;
    int gid = lane >> 2, tig = lane & 3;
    int wr = w & 1, wn = w >> 1;

    // --- hoisted per-thread bases ---
    const uint4* aXi  = XiF + (2 * wr * 16) * 32 + lane;
    const uint4* xjB0 = reinterpret_cast<const uint4*>(smem + SM_XJ0) + (16 * wn + gid) * XP + tig;
    const uint4* xjB1 = reinterpret_cast<const uint4*>(smem + SM_XJ1) + (16 * wn + gid) * XP + tig;
    const uint4* ttB0 = reinterpret_cast<const uint4*>(smem + SM_TT0) + (64 * wn + gid) * TP + tig;
    const uint4* ttB1 = reinterpret_cast<const uint4*>(smem + SM_TT1) + (64 * wn + gid) * TP + tig;
    const uint4* sq0  = reinterpret_cast<const uint4*>(smem + SM_SS0) + (2 * wr * 4) * 32 + lane;
    const uint4* sq1  = reinterpret_cast<const uint4*>(smem + SM_SS1) + (2 * wr * 4) * 32 + lane;
    uint32_t* sst0[4];
    uint32_t* sst1[4];
#pragma unroll
    for (int mb = 0; mb < 2; mb++)
#pragma unroll
        for (int nb = 0; nb < 2; nb++) {
            int gp = 2 * wr + mb;
            int wv = 8 * wn + 4 * nb + tig;
            int qh = wv & 1, ss2 = (wv >> 1) & 1, u = wv >> 2;
            int kc2 = u >> 2, tigc = u & 3;
            int lanec = 4 * gid + tigc;
            uint32_t off = ((uint32_t)(gp * 4 + kc2 * 2 + ss2) * 32 + lanec) * 4 + 2 * qh;
            sst0[mb * 2 + nb] = reinterpret_cast<uint32_t*>(smem + SM_SS0) + off;
            sst1[mb * 2 + nb] = reinterpret_cast<uint32_t*>(smem + SM_SS1) + off;
        }

    // --- strided loaders ---
    const unsigned short* xsrcB = Xg + (size_t)(tid >> 5) * C_DIM + (tid & 31) * 8;
    uint32_t xdst0 = sbase + SM_XJ0 + (uint32_t)((tid >> 5) * XP + (tid & 31)) * 16;
    uint32_t xdst1 = xdst0 + (SM_XJ1 - SM_XJ0);
    const unsigned short* tsrcB = Tg + (size_t)(tid >> 3) * HW_DIM + (tid & 7) * 8;
    uint32_t tdst0 = sbase + SM_TT0 + (uint32_t)((tid >> 3) * TP + (tid & 7)) * 16;
    uint32_t tdst1 = tdst0 + (SM_TT1 - SM_TT0);

    auto loadX = [&](int r0, uint32_t d) {
        const unsigned short* s = xsrcB + (size_t)r0 * C_DIM;
#pragma unroll
        for (int q = 0; q < 8; q++)
            cp16(d + (uint32_t)q * (8 * XP * 16), s + (size_t)q * 8 * C_DIM);
    };
    auto loadT = [&](int j0, uint32_t d) {
        const unsigned short* s = tsrcB + j0;
#pragma unroll
        for (int q = 0; q < 8; q++)
            cp16(d + (uint32_t)q * (32 * TP * 16), s + (size_t)q * 32 * HW_DIM);
    };

    // prologue: g0={Xi(frag),Xj0,T0}, g1={Xj1,T1}
#pragma unroll
    for (int q = 0; q < 8; q++) {
        int idx = tid + q * 256;
        cp16(sbase + SM_XI + (uint32_t)idx * 16, Agm + (size_t)idx * 8);
    }
    loadX(0, xdst0);
    loadT(0, tdst0);
    CP_COMMIT();
    loadX(JT, xdst1);
    loadT(JT, tdst1);
    CP_COMMIT();

    float yacc[2][8][4];
#pragma unroll
    for (int mb = 0; mb < 2; mb++)
#pragma unroll
        for (int nt = 0; nt < 8; nt++)
#pragma unroll
            for (int q = 0; q < 4; q++) yacc[mb][nt][q] = 0.f;

    // ---- iter 0: ph1(0) only -> S0
    CP_WAIT1();
    __syncthreads();
    {
        float sacc[2][2][4] = {};
#pragma unroll
        for (int kc = 0; kc < 8; kc++) {
            uint4 Aq[2][2];
#pragma unroll
            for (int mb = 0; mb < 2; mb++)
#pragma unroll
                for (int ss = 0; ss < 2; ss++)
                    Aq[mb][ss] = aXi[(mb * 16 + 2 * kc + ss) * 32];
            uint4 Bn[2];
#pragma unroll
            for (int nb = 0; nb < 2; nb++)
                Bn[nb] = xjB0[8 * nb * XP + 4 * kc];
#pragma unroll
            for (int ss = 0; ss < 2; ss++)
#pragma unroll
                for (int mb = 0; mb < 2; mb++) {
                    uint4 a = Aq[mb][ss];
#pragma unroll
                    for (int nb = 0; nb < 2; nb++) {
                        const uint32_t* bn = reinterpret_cast<const uint32_t*>(&Bn[nb]);
                        mma16(sacc[mb][nb], a.x, a.y, a.z, a.w, bn[2*ss], bn[2*ss+1]);
                    }
                }
        }
#pragma unroll
        for (int mb = 0; mb < 2; mb++)
#pragma unroll
            for (int nb = 0; nb < 2; nb++) {
                float v0 = fmaxf(sacc[mb][nb][0], 0.f), v1 = fmaxf(sacc[mb][nb][1], 0.f);
                float v2 = fmaxf(sacc[mb][nb][2], 0.f), v3 = fmaxf(sacc[mb][nb][3], 0.f);
                *reinterpret_cast<uint2*>(sst0[mb * 2 + nb]) =
                    make_uint2(h2pack(v0 * v0, v1 * v1), h2pack(v2 * v2, v3 * v3));
            }
    }
    __syncthreads();
    loadX(2 * JT, xdst0);
    CP_COMMIT();
    CP_WAIT1();
    __syncthreads();

    // ---- fused body: ph1(m) + ph2(m-1) interleaved (constant addressing)
    auto body = [&](int m, const uint4* xjB, const uint4* ttB, const uint4* sqR,
                    uint32_t* const* sstP, uint32_t xdst, uint32_t tdst) {
        float sacc[2][2][4] = {};
        uint4 Sq[2][2];
#pragma unroll
        for (int u = 0; u < 8; u++) {
            // chain A: ph1(m) chunk u (8 mma)
            uint4 Aq[2][2];
#pragma unroll
            for (int mb = 0; mb < 2; mb++)
#pragma unroll
                for (int ss = 0; ss < 2; ss++)
                    Aq[mb][ss] = aXi[(mb * 16 + 2 * u + ss) * 32];
            uint4 Bn[2];
#pragma unroll
            for (int nb = 0; nb < 2; nb++)
                Bn[nb] = xjB[8 * nb * XP + 4 * u];
#pragma unroll
            for (int ss = 0; ss < 2; ss++)
#pragma unroll
                for (int mb = 0; mb < 2; mb++) {
                    uint4 a = Aq[mb][ss];
#pragma unroll
                    for (int nb = 0; nb < 2; nb++) {
                        const uint32_t* bn = reinterpret_cast<const uint32_t*>(&Bn[nb]);
                        mma16(sacc[mb][nb], a.x, a.y, a.z, a.w, bn[2*ss], bn[2*ss+1]);
                    }
                }
            // chain B: ph2(m-1) chunk u (4 mma), independent of chain A
            const int kc2 = u >> 2, nt0 = 2 * (u & 3);
            if ((u & 3) == 0) {
#pragma unroll
                for (int mb = 0; mb < 2; mb++)
#pragma unroll
                    for (int ss = 0; ss < 2; ss++)
                        Sq[mb][ss] = sqR[(mb * 4 + kc2 * 2 + ss) * 32];
            }
#pragma unroll
            for (int qq = 0; qq < 2; qq++) {
                const int nt = nt0 + qq;
                uint4 Bv = ttB[8 * nt * TP + 4 * kc2];
                const uint32_t* bn = reinterpret_cast<const uint32_t*>(&Bv);
#pragma unroll
                for (int ss = 0; ss < 2; ss++)
#pragma unroll
                    for (int mb = 0; mb < 2; mb++) {
                        uint4 a = Sq[mb][ss];
                        mma16(yacc[mb][nt], a.x, a.y, a.z, a.w, bn[2*ss], bn[2*ss+1]);
                    }
            }
        }
        // relu^2 -> S[m] (fragment order, precomputed pointers)
#pragma unroll
        for (int mb = 0; mb < 2; mb++)
#pragma unroll
            for (int nb = 0; nb < 2; nb++) {
                float v0 = fmaxf(sacc[mb][nb][0], 0.f), v1 = fmaxf(sacc[mb][nb][1], 0.f);
                float v2 = fmaxf(sacc[mb][nb][2], 0.f), v3 = fmaxf(sacc[mb][nb][3], 0.f);
                *reinterpret_cast<uint2*>(sstP[mb * 2 + nb]) =
                    make_uint2(h2pack(v0 * v0, v1 * v1), h2pack(v2 * v2, v3 * v3));
            }
        __syncthreads();
        if (m + 2 < NJT) loadX((m + 2) * JT, xdst);
        if (m + 1 < NJT) loadT((m + 1) * JT, tdst);
        CP_COMMIT();
        CP_WAIT1();
        __syncthreads();
    };

    // main loop: m = 1..48, unrolled by 2 (odd then even) for constant parity
#pragma unroll 1
    for (int m = 1; m < NJT; m += 2) {
        // m odd: Xj in buf1, T(m-1) in buf0, read S0, write S1; loads -> x1,t0
        body(m,     xjB1, ttB0, sq0, sst1, xdst1, tdst0);
        // m+1 even: Xj in buf0, T(m) in buf1, read S1, write S0; loads -> x0,t1
        body(m + 1, xjB0, ttB1, sq1, sst0, xdst0, tdst1);
    }

    // ---- epilogue: ph2(NJT-1)=ph2(48): T48 in buf0, S in SS0
#pragma unroll
    for (int kc2 = 0; kc2 < 2; kc2++) {
        uint4 Sq[2][2];
#pragma unroll
        for (int mb = 0; mb < 2; mb++)
#pragma unroll
            for (int ss = 0; ss < 2; ss++)
                Sq[mb][ss] = sq0[(mb * 4 + kc2 * 2 + ss) * 32];
#pragma unroll
        for (int nt = 0; nt < 8; nt++) {
            uint4 Bv = ttB0[8 * nt * TP + 4 * kc2];
            const uint32_t* bn = reinterpret_cast<const uint32_t*>(&Bv);
#pragma unroll
            for (int ss = 0; ss < 2; ss++)
#pragma unroll
                for (int mb = 0; mb < 2; mb++) {
                    uint4 a = Sq[mb][ss];
                    mma16(yacc[mb][nt], a.x, a.y, a.z, a.w, bn[2*ss], bn[2*ss+1]);
                }
        }
    }

    // epilogue: write Y
    float* Yb = y + ((size_t)b * HW_DIM + i0) * C_DIM;
#pragma unroll
    for (int mb = 0; mb < 2; mb++) {
        int r1 = 32 * wr + 16 * mb + gid;
#pragma unroll
        for (int nt = 0; nt < 8; nt++) {
            int c = 64 * wn + 8 * nt + 2 * tig;
            *reinterpret_cast<float2*>(&Yb[(size_t)r1 * C_DIM + c]) =
                make_float2(yacc[mb][nt][0], yacc[mb][nt][1]);
            *reinterpret_cast<float2*>(&Yb[(size_t)(r1 + 8) * C_DIM + c]) =
                make_float2(yacc[mb][nt][2], yacc[mb][nt][3]);
        }
    }
}

// ---------------------------------------------------------------------------
extern "C" void kernel_launch(void* const* d_in, const int* in_sizes, int n_in,
                              void* d_out, int out_size) {
    const float* x = (const float*)d_in[0];
    const float* W = (const float*)d_in[1];
    float* y = (float*)d_out;
    (void)in_sizes; (void)n_in; (void)out_size;

    norm_kernel<<<NROWS / 8, dim3(32, 8)>>>(x);
    wt_kernel<<<C_DIM, C_DIM>>>(W);
    xa_kernel<<<NROWS / 64, 256>>>();

    cudaFuncSetAttribute(transform_mma, cudaFuncAttributeMaxDynamicSharedMemorySize, TM_TOT);
    transform_mma<<<NROWS / 64, 256, TM_TOT>>>();

    cudaFuncSetAttribute(ppm_fused, cudaFuncAttributeMaxDynamicSharedMemorySize, SM_TOT);
    ppm_fused<<<dim3(HW_DIM / JT, B_DIM), 256, SM_TOT>>>(y);
}